// round 13
// baseline (speedup 1.0000x reference)
#include <cuda_runtime.h>
#include <cstdint>

typedef unsigned long long ull;

#define NPX 262144   // 4*256*256 pixels

// Conv outputs, transposed [d][px] (static __device__: allocation-guard safe)
__device__ float g_cmt[(size_t)64 * NPX];
__device__ float g_crt[(size_t)64 * NPX];

// ---------------- packed f32x2 helpers ----------------
__device__ __forceinline__ ull fma2(ull a, ull b, ull c) {
    ull d;
    asm("fma.rn.f32x2 %0, %1, %2, %3;" : "=l"(d) : "l"(a), "l"(b), "l"(c));
    return d;
}
__device__ __forceinline__ ull mul2(ull a, ull b) {
    ull d;
    asm("mul.rn.f32x2 %0, %1, %2;" : "=l"(d) : "l"(a), "l"(b));
    return d;
}
__device__ __forceinline__ ull pack2(float x, float y) {
    ull r;
    asm("mov.b64 %0, {%1, %2};" : "=l"(r) : "f"(x), "f"(y));
    return r;
}
__device__ __forceinline__ float2 unpack2(ull v) {
    float2 r;
    asm("mov.b64 {%0, %1}, %2;" : "=f"(r.x), "=f"(r.y) : "l"(v));
    return r;
}

// ---------------- conv kernel v3 (measured ~103-110us): 128 thr, 8px x 8d, float4 A loads ----------------
__global__ void __launch_bounds__(128) conv_kernel(
    const float* __restrict__ main_in, const float* __restrict__ ref_in,
    const float* __restrict__ Wm, const float* __restrict__ Wr)
{
    __shared__ float As[128 * 64];   // [m][c], c float4-groups XOR-swizzled by (m&24)
    __shared__ float Ws[64 * 64];    // [k][d]

    const float* A = blockIdx.y ? ref_in : main_in;
    const float* W = blockIdx.y ? Wr : Wm;
    float* gt      = blockIdx.y ? g_crt : g_cmt;

    int t = threadIdx.x;
    size_t bM = (size_t)blockIdx.x * 128;

    const float4* Ag = (const float4*)(A + bM * 64);
#pragma unroll
    for (int i = 0; i < 16; i++) {
        int idx = i * 128 + t;
        float4 v = Ag[idx];
        int ml = idx >> 4;
        int c0 = (idx & 15) * 4;
        int s = ml & 24;
        *(float4*)&As[ml * 64 + (c0 ^ s)] = v;
    }
    const float4* Wg4 = (const float4*)W;
    float4* Ws4 = (float4*)Ws;
#pragma unroll
    for (int i = 0; i < 8; i++)
        Ws4[i * 128 + t] = Wg4[i * 128 + t];

    __syncthreads();

    int tn = t & 7;
    int tm = t >> 3;
    int sw = (tm & 3) << 3;

    ull acc[8][4];
#pragma unroll
    for (int p = 0; p < 8; p++)
#pragma unroll
        for (int j = 0; j < 4; j++) acc[p][j] = 0ull;

    const float* arow = &As[(tm * 8) * 64];

#pragma unroll 4
    for (int k4 = 0; k4 < 16; k4++) {
        float4 a4[8];
        int sk = (k4 * 4) ^ sw;
#pragma unroll
        for (int p = 0; p < 8; p++)
            a4[p] = *(const float4*)&arow[p * 64 + sk];
#pragma unroll
        for (int kk = 0; kk < 4; kk++) {
            int k = k4 * 4 + kk;
            ulonglong2 w01 = *(const ulonglong2*)&Ws[k * 64 + tn * 4];
            ulonglong2 w23 = *(const ulonglong2*)&Ws[k * 64 + 32 + tn * 4];
#pragma unroll
            for (int p = 0; p < 8; p++) {
                float a = (kk == 0) ? a4[p].x : (kk == 1) ? a4[p].y
                        : (kk == 2) ? a4[p].z : a4[p].w;
                ull av = pack2(a, a);
                acc[p][0] = fma2(av, w01.x, acc[p][0]);
                acc[p][1] = fma2(av, w01.y, acc[p][1]);
                acc[p][2] = fma2(av, w23.x, acc[p][2]);
                acc[p][3] = fma2(av, w23.y, acc[p][3]);
            }
        }
    }

    size_t pxb = bM + tm * 8;
    int dbase[4] = { tn * 4, tn * 4 + 2, 32 + tn * 4, 32 + tn * 4 + 2 };
#pragma unroll
    for (int j = 0; j < 4; j++) {
        float2 f[8];
#pragma unroll
        for (int p = 0; p < 8; p++) f[p] = unpack2(acc[p][j]);
        float* o0 = gt + (size_t)dbase[j] * NPX + pxb;
        float* o1 = o0 + (size_t)NPX;
        *(float4*)o0       = make_float4(f[0].x, f[1].x, f[2].x, f[3].x);
        *(float4*)(o0 + 4) = make_float4(f[4].x, f[5].x, f[6].x, f[7].x);
        *(float4*)o1       = make_float4(f[0].y, f[1].y, f[2].y, f[3].y);
        *(float4*)(o1 + 4) = make_float4(f[4].y, f[5].y, f[6].y, f[7].y);
    }
}

// ---------------- attention kernel v8: pair-plane logit (v5) + attn7 epilogue ----------------
// Tile 32x16 = 512 px, thread = 2-px horizontal pair.
// Pair planes: pp[c][row][x] = (v[x], v[x+1]) as ull; 8 channels/chunk, 8 chunks.
// ps (unioned): probs [25][520] floats.
#define TW 32
#define TH 16
#define HH 20
#define PPW 40                     // pair-plane row stride (pairs)
#define CCH 8
#define PPLANE (HH * PPW)          // 800 ull per channel
#define PP_BYTES (CCH * PPLANE * 8)        // 51,200
#define PSS 520
#define PS_BYTES (25 * PSS * 4)            // 54,080
#define UNION_BYTES 54080                  // max(PP_BYTES, PS_BYTES)
#define SMEM_ATTN (UNION_BYTES + 1600 * 4) // 60,480

__global__ void __launch_bounds__(256, 2) attn8_kernel(
    const float* __restrict__ Wg, float* __restrict__ out)
{
    extern __shared__ char smraw[];
    ull* pp    = (ull*)smraw;
    float* ps  = (float*)smraw;
    float* Wgs = (float*)(smraw + UNION_BYTES);

    int t = threadIdx.x;
    int bx = blockIdx.x, by = blockIdx.y, b = blockIdx.z;
    int strip = t & 15, row = t >> 4;
    int x0 = strip * 2;
    int gy = by * TH + row;
    int gx0 = bx * TW + x0;
    size_t px0g = ((size_t)b * 256 + gy) * 256 + gx0;
    int lp0 = row * TW + x0;

    for (int i = t; i < 1600; i += 256) Wgs[i] = Wg[i];

    ull acc[25];
#pragma unroll
    for (int i = 0; i < 25; i++) acc[i] = 0ull;

    int y0t = by * TH - 2;

#pragma unroll 1
    for (int cc = 0; cc < 8; cc++) {
        __syncthreads();
        // ---- fill pair planes: jobs = 8 ch * 20 rows * 10 quads ----
        for (int f = t; f < CCH * HH * 10; f += 256) {
            int q = f % 10;
            int rh = f / 10;
            int hy = rh % HH;
            int c = rh / HH;
            int gyh = y0t + hy;
            int gxb = bx * TW - 4 + q * 4;     // 16B-aligned gmem base
            float vv[4] = {0.f, 0.f, 0.f, 0.f};
            float v4 = 0.f;
            if (gyh >= 0 && gyh < 256) {
                const float* pl = g_crt + (size_t)(cc * CCH + c) * NPX
                                        + ((size_t)b * 256 + gyh) * 256;
                if (gxb >= 0 && gxb + 3 < 256) {
                    float4 v = *(const float4*)(pl + gxb);
                    vv[0] = v.x; vv[1] = v.y; vv[2] = v.z; vv[3] = v.w;
                } else {
#pragma unroll
                    for (int j = 0; j < 4; j++) {
                        int gx = gxb + j;
                        if (gx >= 0 && gx < 256) vv[j] = pl[gx];
                    }
                }
                int gx4 = gxb + 4;
                if (gx4 >= 0 && gx4 < 256) v4 = pl[gx4];
            }
            ull* dst = &pp[c * PPLANE + hy * PPW];
#pragma unroll
            for (int j = 0; j < 4; j++) {
                int sx = q * 4 + j - 2;        // pair index = gx - (bx*TW - 2)
                if (sx >= 0 && sx < 35) {
                    float hi = (j < 3) ? vv[j + 1] : v4;
                    dst[sx] = pack2(vv[j], hi);
                }
            }
        }
        __syncthreads();

        // ---- accumulate logits (taps pre-paired: 3 LDS + 5 fma2 per r, zero packs) ----
        const float* cmp = g_cmt + (size_t)(cc * CCH) * NPX + px0g;
        ull cm2 = *(const ull*)cmp;
#pragma unroll 4
        for (int c = 0; c < CCH; c++) {
            ull cur = cm2;
            if (c + 1 < CCH)
                cm2 = *(const ull*)(cmp + (size_t)(c + 1) * NPX);
            const ull* cr = &pp[c * PPLANE + row * PPW + x0];
#pragma unroll
            for (int r = 0; r < 5; r++) {
                ulonglong2 q01 = *(const ulonglong2*)(cr + r * PPW);
                ulonglong2 q23 = *(const ulonglong2*)(cr + r * PPW + 2);
                ull q4 = cr[r * PPW + 4];
                acc[r * 5 + 0] = fma2(cur, q01.x, acc[r * 5 + 0]);
                acc[r * 5 + 1] = fma2(cur, q01.y, acc[r * 5 + 1]);
                acc[r * 5 + 2] = fma2(cur, q23.x, acc[r * 5 + 2]);
                acc[r * 5 + 3] = fma2(cur, q23.y, acc[r * 5 + 3]);
                acc[r * 5 + 4] = fma2(cur, q4,    acc[r * 5 + 4]);
            }
        }
    }

    // ---- softmax over 25 (lanes = the two pixels) ----
    {
        float mA = -1e30f, mB = -1e30f;
#pragma unroll
        for (int kk = 0; kk < 25; kk++) {
            float2 v = unpack2(acc[kk]);
            mA = fmaxf(mA, v.x); mB = fmaxf(mB, v.y);
        }
        float sA = 0.f, sB = 0.f;
#pragma unroll
        for (int kk = 0; kk < 25; kk++) {
            float2 v = unpack2(acc[kk]);
            float eA = __expf(v.x - mA), eB = __expf(v.y - mB);
            sA += eA; sB += eB;
            acc[kk] = pack2(eA, eB);
        }
        ull iv = pack2(__fdividef(1.f, sA), __fdividef(1.f, sB));
#pragma unroll
        for (int kk = 0; kk < 25; kk++)
            acc[kk] = mul2(acc[kk], iv);
    }

    // ---- transpose probs to smem: ps[kk][lp] (overwrites pp) ----
    __syncthreads();
#pragma unroll
    for (int kk = 0; kk < 25; kk++)
        *(ull*)&ps[kk * PSS + lp0] = acc[kk];
    __syncthreads();

    // ---- out = attn @ Wg: warp w -> rows 2w,2w+1; lane l -> d=l, d=l+32 ----
    {
        int w = t >> 5, l = t & 31;
        ull wr0[25], wr1[25];
#pragma unroll
        for (int kk = 0; kk < 25; kk++) {
            float w0 = Wgs[kk * 64 + l];
            float w1 = Wgs[kk * 64 + 32 + l];
            wr0[kk] = pack2(w0, w0);
            wr1[kk] = pack2(w1, w1);
        }
#pragma unroll 1
        for (int rr = 0; rr < 2; rr++) {
            int lrow = w * 2 + rr;
            int lpbase = lrow * TW;
            size_t grow = ((size_t)b * 256 + by * TH + lrow) * 256 + bx * TW;
            float* outp = out + grow * 64;
#pragma unroll 1
            for (int ii = 0; ii < 8; ii++) {
                ull oa0 = 0, oa1 = 0, ob0 = 0, ob1 = 0;
                const float* psp = ps + lpbase + ii * 4;
#pragma unroll
                for (int kk = 0; kk < 25; kk++) {
                    ulonglong2 pq = *(const ulonglong2*)(psp + kk * PSS);
                    oa0 = fma2(pq.x, wr0[kk], oa0);
                    oa1 = fma2(pq.x, wr1[kk], oa1);
                    ob0 = fma2(pq.y, wr0[kk], ob0);
                    ob1 = fma2(pq.y, wr1[kk], ob1);
                }
                float2 a0 = unpack2(oa0), a1 = unpack2(oa1);
                float2 b0 = unpack2(ob0), b1 = unpack2(ob1);
                float* o0 = outp + (ii * 4) * 64;
                o0[l]       = a0.x;   // px+0, d=l
                o0[64 + l]  = a0.y;   // px+1, d=l
                o0[32 + l]  = a1.x;   // px+0, d=l+32
                o0[96 + l]  = a1.y;   // px+1, d=l+32
                o0[128 + l] = b0.x;   // px+2, d=l
                o0[192 + l] = b0.y;   // px+3, d=l
                o0[160 + l] = b1.x;   // px+2, d=l+32
                o0[224 + l] = b1.y;   // px+3, d=l+32
            }
        }
    }
}

// ---------------- launch ----------------
extern "C" void kernel_launch(void* const* d_in, const int* in_sizes, int n_in,
                              void* d_out, int out_size)
{
    const float* main_in = (const float*)d_in[0];
    const float* ref_in  = (const float*)d_in[1];
    const float* Wm      = (const float*)d_in[2];
    const float* Wr      = (const float*)d_in[3];
    const float* Wg      = (const float*)d_in[4];
    float* out = (float*)d_out;

    conv_kernel<<<dim3(2048, 2), 128>>>(main_in, ref_in, Wm, Wr);

    cudaFuncSetAttribute(attn8_kernel, cudaFuncAttributeMaxDynamicSharedMemorySize, SMEM_ATTN);
    attn8_kernel<<<dim3(8, 16, 4), 256, SMEM_ATTN>>>(Wg, out);
}

// round 14
// speedup vs baseline: 1.0614x; 1.0614x over previous
#include <cuda_runtime.h>
#include <cstdint>

typedef unsigned long long ull;

#define NPX 262144   // 4*256*256 pixels

// Conv outputs, transposed [d][px] (static __device__: allocation-guard safe)
__device__ float g_cmt[(size_t)64 * NPX];
__device__ float g_crt[(size_t)64 * NPX];

// ---------------- packed f32x2 helpers ----------------
__device__ __forceinline__ ull fma2(ull a, ull b, ull c) {
    ull d;
    asm("fma.rn.f32x2 %0, %1, %2, %3;" : "=l"(d) : "l"(a), "l"(b), "l"(c));
    return d;
}
__device__ __forceinline__ ull add2(ull a, ull b) {
    ull d;
    asm("add.rn.f32x2 %0, %1, %2;" : "=l"(d) : "l"(a), "l"(b));
    return d;
}
__device__ __forceinline__ ull mul2(ull a, ull b) {
    ull d;
    asm("mul.rn.f32x2 %0, %1, %2;" : "=l"(d) : "l"(a), "l"(b));
    return d;
}
__device__ __forceinline__ ull pack2(float x, float y) {
    ull r;
    asm("mov.b64 %0, {%1, %2};" : "=l"(r) : "f"(x), "f"(y));
    return r;
}
__device__ __forceinline__ float2 unpack2(ull v) {
    float2 r;
    asm("mov.b64 {%0, %1}, %2;" : "=f"(r.x), "=f"(r.y) : "l"(v));
    return r;
}

// ---------------- conv kernel v3 (measured ~103us): 128 thr, 8px x 8d, float4 A loads ----------------
__global__ void __launch_bounds__(128) conv_kernel(
    const float* __restrict__ main_in, const float* __restrict__ ref_in,
    const float* __restrict__ Wm, const float* __restrict__ Wr)
{
    __shared__ float As[128 * 64];   // [m][c], c float4-groups XOR-swizzled by (m&24)
    __shared__ float Ws[64 * 64];    // [k][d]

    const float* A = blockIdx.y ? ref_in : main_in;
    const float* W = blockIdx.y ? Wr : Wm;
    float* gt      = blockIdx.y ? g_crt : g_cmt;

    int t = threadIdx.x;
    size_t bM = (size_t)blockIdx.x * 128;

    const float4* Ag = (const float4*)(A + bM * 64);
#pragma unroll
    for (int i = 0; i < 16; i++) {
        int idx = i * 128 + t;
        float4 v = Ag[idx];
        int ml = idx >> 4;
        int c0 = (idx & 15) * 4;
        int s = ml & 24;
        *(float4*)&As[ml * 64 + (c0 ^ s)] = v;
    }
    const float4* Wg4 = (const float4*)W;
    float4* Ws4 = (float4*)Ws;
#pragma unroll
    for (int i = 0; i < 8; i++)
        Ws4[i * 128 + t] = Wg4[i * 128 + t];

    __syncthreads();

    int tn = t & 7;
    int tm = t >> 3;
    int sw = (tm & 3) << 3;

    ull acc[8][4];
#pragma unroll
    for (int p = 0; p < 8; p++)
#pragma unroll
        for (int j = 0; j < 4; j++) acc[p][j] = 0ull;

    const float* arow = &As[(tm * 8) * 64];

#pragma unroll 4
    for (int k4 = 0; k4 < 16; k4++) {
        float4 a4[8];
        int sk = (k4 * 4) ^ sw;
#pragma unroll
        for (int p = 0; p < 8; p++)
            a4[p] = *(const float4*)&arow[p * 64 + sk];
#pragma unroll
        for (int kk = 0; kk < 4; kk++) {
            int k = k4 * 4 + kk;
            ulonglong2 w01 = *(const ulonglong2*)&Ws[k * 64 + tn * 4];
            ulonglong2 w23 = *(const ulonglong2*)&Ws[k * 64 + 32 + tn * 4];
#pragma unroll
            for (int p = 0; p < 8; p++) {
                float a = (kk == 0) ? a4[p].x : (kk == 1) ? a4[p].y
                        : (kk == 2) ? a4[p].z : a4[p].w;
                ull av = pack2(a, a);
                acc[p][0] = fma2(av, w01.x, acc[p][0]);
                acc[p][1] = fma2(av, w01.y, acc[p][1]);
                acc[p][2] = fma2(av, w23.x, acc[p][2]);
                acc[p][3] = fma2(av, w23.y, acc[p][3]);
            }
        }
    }

    size_t pxb = bM + tm * 8;
    int dbase[4] = { tn * 4, tn * 4 + 2, 32 + tn * 4, 32 + tn * 4 + 2 };
#pragma unroll
    for (int j = 0; j < 4; j++) {
        float2 f[8];
#pragma unroll
        for (int p = 0; p < 8; p++) f[p] = unpack2(acc[p][j]);
        float* o0 = gt + (size_t)dbase[j] * NPX + pxb;
        float* o1 = o0 + (size_t)NPX;
        *(float4*)o0       = make_float4(f[0].x, f[1].x, f[2].x, f[3].x);
        *(float4*)(o0 + 4) = make_float4(f[4].x, f[5].x, f[6].x, f[7].x);
        *(float4*)o1       = make_float4(f[0].y, f[1].y, f[2].y, f[3].y);
        *(float4*)(o1 + 4) = make_float4(f[4].y, f[5].y, f[6].y, f[7].y);
    }
}

// ---------------- attention kernel v9: v7 structure + split-K over 2 thread-halves ----------------
// 512 threads: t = kh*256 + u; u = px-pair (strip,row) in 32x16 tile; kh = channel half.
// Round rr (0,1): fill crs with channels rr*32..rr*32+31; thread accumulates
// its 16 channels (rr*32 + kh*16 ..+16). Then smem reduction kh1->kh0, softmax
// on kh0, ps transpose, out-stage over 16 warps (1 row each).
#define TW 32
#define TH 16
#define HH 20
#define HWS 40
#define PLANE 800              // floats per channel plane (HH*HWS)
#define NCH_R 32               // channels per round
#define PSS 520
// smem byte layout
#define CRS_BYTES (NCH_R * PLANE * 4)      // 102,400
#define RED_OFF   0                        // 25*256 ull = 51,200 (aliases crs)
#define PS_OFF    51200                    // 25*520*4 = 54,080 -> end 105,280
#define WGS_OFF   105280                   // 1600*4 = 6,400
#define SMEM_ATTN 111680

__global__ void __launch_bounds__(512, 1) attn9_kernel(
    const float* __restrict__ Wg, float* __restrict__ out)
{
    extern __shared__ char smraw[];
    float* crs = (float*)smraw;
    ull*   red = (ull*)(smraw + RED_OFF);
    float* ps  = (float*)(smraw + PS_OFF);
    float* Wgs = (float*)(smraw + WGS_OFF);

    int t = threadIdx.x;
    int kh = t >> 8;           // channel half
    int u  = t & 255;          // px-pair id
    int bx = blockIdx.x, by = blockIdx.y, b = blockIdx.z;
    int strip = u & 15, row = u >> 4;
    int x0 = strip * 2;
    int gy = by * TH + row;
    int gx0 = bx * TW + x0;
    size_t px0g = ((size_t)b * 256 + gy) * 256 + gx0;
    int lp0 = row * TW + x0;

    for (int i = t; i < 1600; i += 512) Wgs[i] = Wg[i];

    ull acc[25];
#pragma unroll
    for (int i = 0; i < 25; i++) acc[i] = 0ull;

    int y0t = by * TH - 2;

#pragma unroll 1
    for (int rr = 0; rr < 2; rr++) {
        __syncthreads();
        // ---- fill 32 halo planes: jobs = 32 ch * 20 rows * 10 quads = 6400 ----
        for (int f = t; f < NCH_R * HH * 10; f += 512) {
            int q = f % 10;
            int rh = f / 10;
            int hy = rh % HH;
            int c = rh / HH;                    // plane 0..31
            int gyh = y0t + hy;
            int gxb = bx * TW - 4 + q * 4;
            float vv[4] = {0.f, 0.f, 0.f, 0.f};
            if (gyh >= 0 && gyh < 256) {
                const float* pl = g_crt + (size_t)(rr * NCH_R + c) * NPX
                                        + ((size_t)b * 256 + gyh) * 256;
                if (gxb >= 0 && gxb + 3 < 256) {
                    float4 v = *(const float4*)(pl + gxb);
                    vv[0] = v.x; vv[1] = v.y; vv[2] = v.z; vv[3] = v.w;
                } else {
#pragma unroll
                    for (int j = 0; j < 4; j++) {
                        int gx = gxb + j;
                        if (gx >= 0 && gx < 256) vv[j] = pl[gx];
                    }
                }
            }
            float* dst = &crs[c * PLANE + hy * HWS];
#pragma unroll
            for (int j = 0; j < 4; j++) {
                int sx = q * 4 + j - 2;
                if (sx >= 0 && sx < 36) dst[sx] = vv[j];
            }
        }
        __syncthreads();

        // ---- accumulate my 16 channels (planes kh*16 .. +15), prefetch-1 on cm ----
        const float* cmp = g_cmt + (size_t)(rr * NCH_R + kh * 16) * NPX + px0g;
        ull cm2 = *(const ull*)cmp;
#pragma unroll 4
        for (int c = 0; c < 16; c++) {
            ull cur = cm2;
            if (c + 1 < 16)
                cm2 = *(const ull*)(cmp + (size_t)(c + 1) * NPX);
            const float* cr = &crs[(kh * 16 + c) * PLANE + row * HWS + x0];
#pragma unroll
            for (int r = 0; r < 5; r++) {
                float2 A = *(const float2*)(cr + r * HWS);
                float2 B = *(const float2*)(cr + r * HWS + 2);
                float2 C = *(const float2*)(cr + r * HWS + 4);
                ull k0 = pack2(A.x, A.y);
                ull k1 = pack2(A.y, B.x);
                ull k2 = pack2(B.x, B.y);
                ull k3 = pack2(B.y, C.x);
                ull k4 = pack2(C.x, C.y);
                acc[r * 5 + 0] = fma2(cur, k0, acc[r * 5 + 0]);
                acc[r * 5 + 1] = fma2(cur, k1, acc[r * 5 + 1]);
                acc[r * 5 + 2] = fma2(cur, k2, acc[r * 5 + 2]);
                acc[r * 5 + 3] = fma2(cur, k3, acc[r * 5 + 3]);
                acc[r * 5 + 4] = fma2(cur, k4, acc[r * 5 + 4]);
            }
        }
    }

    // ---- reduction: kh1 -> smem, kh0 adds (kk-major: conflict-free STS/LDS.64) ----
    __syncthreads();   // crs dead
    if (kh == 1) {
#pragma unroll
        for (int kk = 0; kk < 25; kk++)
            red[kk * 256 + u] = acc[kk];
    }
    __syncthreads();
    if (kh == 0) {
#pragma unroll
        for (int kk = 0; kk < 25; kk++)
            acc[kk] = add2(acc[kk], red[kk * 256 + u]);

        // ---- softmax over 25 (lanes = the two pixels) ----
        float mA = -1e30f, mB = -1e30f;
#pragma unroll
        for (int kk = 0; kk < 25; kk++) {
            float2 v = unpack2(acc[kk]);
            mA = fmaxf(mA, v.x); mB = fmaxf(mB, v.y);
        }
        float sA = 0.f, sB = 0.f;
#pragma unroll
        for (int kk = 0; kk < 25; kk++) {
            float2 v = unpack2(acc[kk]);
            float eA = __expf(v.x - mA), eB = __expf(v.y - mB);
            sA += eA; sB += eB;
            acc[kk] = pack2(eA, eB);
        }
        ull iv = pack2(__fdividef(1.f, sA), __fdividef(1.f, sB));

        // ---- write probs transposed: ps[kk][lp] ----
#pragma unroll
        for (int kk = 0; kk < 25; kk++)
            *(ull*)&ps[kk * PSS + lp0] = mul2(acc[kk], iv);
    }
    __syncthreads();

    // ---- out = attn @ Wg: warp w -> row w (32 px); lane l -> d=l, d=l+32 ----
    {
        int w = t >> 5, l = t & 31;
        ull wr0[25], wr1[25];
#pragma unroll
        for (int kk = 0; kk < 25; kk++) {
            float w0 = Wgs[kk * 64 + l];
            float w1 = Wgs[kk * 64 + 32 + l];
            wr0[kk] = pack2(w0, w0);
            wr1[kk] = pack2(w1, w1);
        }
        int lpbase = w * TW;
        size_t grow = ((size_t)b * 256 + by * TH + w) * 256 + bx * TW;
        float* outp = out + grow * 64;
#pragma unroll 1
        for (int ii = 0; ii < 8; ii++) {
            ull oa0 = 0, oa1 = 0, ob0 = 0, ob1 = 0;
            const float* psp = ps + lpbase + ii * 4;
#pragma unroll
            for (int kk = 0; kk < 25; kk++) {
                ulonglong2 pq = *(const ulonglong2*)(psp + kk * PSS);
                oa0 = fma2(pq.x, wr0[kk], oa0);
                oa1 = fma2(pq.x, wr1[kk], oa1);
                ob0 = fma2(pq.y, wr0[kk], ob0);
                ob1 = fma2(pq.y, wr1[kk], ob1);
            }
            float2 a0 = unpack2(oa0), a1 = unpack2(oa1);
            float2 b0 = unpack2(ob0), b1 = unpack2(ob1);
            float* o0 = outp + (ii * 4) * 64;
            o0[l]       = a0.x;   // px+0, d=l
            o0[64 + l]  = a0.y;   // px+1, d=l
            o0[32 + l]  = a1.x;   // px+0, d=l+32
            o0[96 + l]  = a1.y;   // px+1, d=l+32
            o0[128 + l] = b0.x;   // px+2, d=l
            o0[192 + l] = b0.y;   // px+3, d=l
            o0[160 + l] = b1.x;   // px+2, d=l+32
            o0[224 + l] = b1.y;   // px+3, d=l+32
        }
    }
}

// ---------------- launch ----------------
extern "C" void kernel_launch(void* const* d_in, const int* in_sizes, int n_in,
                              void* d_out, int out_size)
{
    const float* main_in = (const float*)d_in[0];
    const float* ref_in  = (const float*)d_in[1];
    const float* Wm      = (const float*)d_in[2];
    const float* Wr      = (const float*)d_in[3];
    const float* Wg      = (const float*)d_in[4];
    float* out = (float*)d_out;

    conv_kernel<<<dim3(2048, 2), 128>>>(main_in, ref_in, Wm, Wr);

    cudaFuncSetAttribute(attn9_kernel, cudaFuncAttributeMaxDynamicSharedMemorySize, SMEM_ATTN);
    attn9_kernel<<<dim3(8, 16, 4), 512, SMEM_ATTN>>>(Wg, out);
}

// round 15
// speedup vs baseline: 1.3298x; 1.2529x over previous
#include <cuda_runtime.h>
#include <cstdint>

typedef unsigned long long ull;

#define NPX 262144   // 4*256*256 pixels

// Static scratch (allocation-guard safe)
__device__ float g_crt[(size_t)64 * NPX];   // cr2 = ref @ M^T, transposed [c][px]
__device__ float g_W2[64 * 64];             // W2[e][c] = M_{c,e} = sum_d Wm[c][d]*Wr[e][d]

// ---------------- packed f32x2 helpers ----------------
__device__ __forceinline__ ull fma2(ull a, ull b, ull c) {
    ull d;
    asm("fma.rn.f32x2 %0, %1, %2, %3;" : "=l"(d) : "l"(a), "l"(b), "l"(c));
    return d;
}
__device__ __forceinline__ ull mul2(ull a, ull b) {
    ull d;
    asm("mul.rn.f32x2 %0, %1, %2;" : "=l"(d) : "l"(a), "l"(b));
    return d;
}
__device__ __forceinline__ ull pack2(float x, float y) {
    ull r;
    asm("mov.b64 %0, {%1, %2};" : "=l"(r) : "f"(x), "f"(y));
    return r;
}
__device__ __forceinline__ float2 unpack2(ull v) {
    float2 r;
    asm("mov.b64 {%0, %1}, %2;" : "=f"(r.x), "=f"(r.y) : "l"(v));
    return r;
}

// ---------------- M kernel: g_W2[e*64+c] = sum_d Wm[c*64+d] * Wr[e*64+d] ----------------
__global__ void __launch_bounds__(256) compute_M_kernel(
    const float* __restrict__ Wm, const float* __restrict__ Wr)
{
    int tid = blockIdx.x * 256 + threadIdx.x;   // 0..4095
    int e = tid >> 6, c = tid & 63;
    const float4* wc = (const float4*)(Wm + c * 64);
    const float4* we = (const float4*)(Wr + e * 64);
    float s = 0.f;
#pragma unroll
    for (int d4 = 0; d4 < 16; d4++) {
        float4 a = wc[d4], b = we[d4];
        s += a.x * b.x + a.y * b.y + a.z * b.z + a.w * b.w;
    }
    g_W2[tid] = s;
}

// ---------------- conv kernel (single GEMM): g_crt[c][px] = sum_e ref[px][e] * W2[e][c] ----------------
__global__ void __launch_bounds__(128) conv_kernel(const float* __restrict__ ref_in)
{
    __shared__ float As[128 * 64];   // [m][e], e float4-groups XOR-swizzled by (m&24)
    __shared__ float Ws[64 * 64];    // [e][c]

    int t = threadIdx.x;
    size_t bM = (size_t)blockIdx.x * 128;

    const float4* Ag = (const float4*)(ref_in + bM * 64);
#pragma unroll
    for (int i = 0; i < 16; i++) {
        int idx = i * 128 + t;
        float4 v = Ag[idx];
        int ml = idx >> 4;
        int c0 = (idx & 15) * 4;
        int s = ml & 24;
        *(float4*)&As[ml * 64 + (c0 ^ s)] = v;
    }
    const float4* Wg4 = (const float4*)g_W2;
    float4* Ws4 = (float4*)Ws;
#pragma unroll
    for (int i = 0; i < 8; i++)
        Ws4[i * 128 + t] = Wg4[i * 128 + t];

    __syncthreads();

    int tn = t & 7;
    int tm = t >> 3;
    int sw = (tm & 3) << 3;

    ull acc[8][4];
#pragma unroll
    for (int p = 0; p < 8; p++)
#pragma unroll
        for (int j = 0; j < 4; j++) acc[p][j] = 0ull;

    const float* arow = &As[(tm * 8) * 64];

#pragma unroll 4
    for (int k4 = 0; k4 < 16; k4++) {
        float4 a4[8];
        int sk = (k4 * 4) ^ sw;
#pragma unroll
        for (int p = 0; p < 8; p++)
            a4[p] = *(const float4*)&arow[p * 64 + sk];
#pragma unroll
        for (int kk = 0; kk < 4; kk++) {
            int k = k4 * 4 + kk;
            ulonglong2 w01 = *(const ulonglong2*)&Ws[k * 64 + tn * 4];
            ulonglong2 w23 = *(const ulonglong2*)&Ws[k * 64 + 32 + tn * 4];
#pragma unroll
            for (int p = 0; p < 8; p++) {
                float a = (kk == 0) ? a4[p].x : (kk == 1) ? a4[p].y
                        : (kk == 2) ? a4[p].z : a4[p].w;
                ull av = pack2(a, a);
                acc[p][0] = fma2(av, w01.x, acc[p][0]);
                acc[p][1] = fma2(av, w01.y, acc[p][1]);
                acc[p][2] = fma2(av, w23.x, acc[p][2]);
                acc[p][3] = fma2(av, w23.y, acc[p][3]);
            }
        }
    }

    size_t pxb = bM + tm * 8;
    int dbase[4] = { tn * 4, tn * 4 + 2, 32 + tn * 4, 32 + tn * 4 + 2 };
#pragma unroll
    for (int j = 0; j < 4; j++) {
        float2 f[8];
#pragma unroll
        for (int p = 0; p < 8; p++) f[p] = unpack2(acc[p][j]);
        float* o0 = g_crt + (size_t)dbase[j] * NPX + pxb;
        float* o1 = o0 + (size_t)NPX;
        *(float4*)o0       = make_float4(f[0].x, f[1].x, f[2].x, f[3].x);
        *(float4*)(o0 + 4) = make_float4(f[4].x, f[5].x, f[6].x, f[7].x);
        *(float4*)o1       = make_float4(f[0].y, f[1].y, f[2].y, f[3].y);
        *(float4*)(o1 + 4) = make_float4(f[4].y, f[5].y, f[6].y, f[7].y);
    }
}

// ---------------- attention kernel v10: v7 structure, cm side reads raw main ----------------
#define TW 32
#define TH 16
#define HH 20
#define HWS 40
#define CCH 16
#define PLANE 800          // HH*HWS
#define PSS 520
#define UNION_FLOATS 13000 // max(16*800=12800, 25*520=13000)

__global__ void __launch_bounds__(256, 2) attn10_kernel(
    const float* __restrict__ main_in, const float* __restrict__ Wg,
    float* __restrict__ out)
{
    extern __shared__ float asmem[];
    float* crs = asmem;
    float* ps  = asmem;
    float* Wgs = asmem + UNION_FLOATS;

    int t = threadIdx.x;
    int bx = blockIdx.x, by = blockIdx.y, b = blockIdx.z;
    int strip = t & 15, row = t >> 4;
    int x0 = strip * 2;
    int gy = by * TH + row;
    int gx0 = bx * TW + x0;
    size_t px0g = ((size_t)b * 256 + gy) * 256 + gx0;
    int lp0 = row * TW + x0;

    for (int i = t; i < 1600; i += 256) Wgs[i] = Wg[i];

    ull acc[25];
#pragma unroll
    for (int i = 0; i < 25; i++) acc[i] = 0ull;

    int y0t = by * TH - 2;

#pragma unroll 1
    for (int cc = 0; cc < 4; cc++) {
        __syncthreads();
        // ---- fill halo planes from cr2: jobs = 16 ch * 20 rows * 10 quads ----
        for (int f = t; f < CCH * HH * 10; f += 256) {
            int q = f % 10;
            int rh = f / 10;
            int hy = rh % HH;
            int c = rh / HH;
            int gyh = y0t + hy;
            int gxb = bx * TW - 4 + q * 4;
            float vv[4] = {0.f, 0.f, 0.f, 0.f};
            if (gyh >= 0 && gyh < 256) {
                const float* pl = g_crt + (size_t)(cc * CCH + c) * NPX
                                        + ((size_t)b * 256 + gyh) * 256;
                if (gxb >= 0 && gxb + 3 < 256) {
                    float4 v = *(const float4*)(pl + gxb);
                    vv[0] = v.x; vv[1] = v.y; vv[2] = v.z; vv[3] = v.w;
                } else {
#pragma unroll
                    for (int j = 0; j < 4; j++) {
                        int gx = gxb + j;
                        if (gx >= 0 && gx < 256) vv[j] = pl[gx];
                    }
                }
            }
            float* dst = &crs[c * PLANE + hy * HWS];
#pragma unroll
            for (int j = 0; j < 4; j++) {
                int sx = q * 4 + j - 2;
                if (sx >= 0 && sx < 36) dst[sx] = vv[j];
            }
        }
        __syncthreads();

        // ---- accumulate logits; cm side = raw main rows (contiguous), prefetch-1 ----
        const float* mpa = main_in + px0g * 64 + cc * 16;   // my px0 channels cc*16..+15
        const float* mpb = mpa + 64;                        // my px1
        float4 va = *(const float4*)mpa;
        float4 vb = *(const float4*)mpb;
#pragma unroll
        for (int c4 = 0; c4 < 4; c4++) {
            float4 ca = va, cb = vb;
            if (c4 + 1 < 4) {
                va = *(const float4*)(mpa + (c4 + 1) * 4);
                vb = *(const float4*)(mpb + (c4 + 1) * 4);
            }
#pragma unroll
            for (int j = 0; j < 4; j++) {
                float fa = (j == 0) ? ca.x : (j == 1) ? ca.y : (j == 2) ? ca.z : ca.w;
                float fb = (j == 0) ? cb.x : (j == 1) ? cb.y : (j == 2) ? cb.z : cb.w;
                ull cur = pack2(fa, fb);
                const float* cr = &crs[(c4 * 4 + j) * PLANE + row * HWS + x0];
#pragma unroll
                for (int r = 0; r < 5; r++) {
                    float2 A = *(const float2*)(cr + r * HWS);
                    float2 B = *(const float2*)(cr + r * HWS + 2);
                    float2 C = *(const float2*)(cr + r * HWS + 4);
                    ull k0 = pack2(A.x, A.y);
                    ull k1 = pack2(A.y, B.x);
                    ull k2 = pack2(B.x, B.y);
                    ull k3 = pack2(B.y, C.x);
                    ull k4 = pack2(C.x, C.y);
                    acc[r * 5 + 0] = fma2(cur, k0, acc[r * 5 + 0]);
                    acc[r * 5 + 1] = fma2(cur, k1, acc[r * 5 + 1]);
                    acc[r * 5 + 2] = fma2(cur, k2, acc[r * 5 + 2]);
                    acc[r * 5 + 3] = fma2(cur, k3, acc[r * 5 + 3]);
                    acc[r * 5 + 4] = fma2(cur, k4, acc[r * 5 + 4]);
                }
            }
        }
    }

    // ---- softmax over 25 (lanes = the two pixels) ----
    {
        float mA = -1e30f, mB = -1e30f;
#pragma unroll
        for (int kk = 0; kk < 25; kk++) {
            float2 v = unpack2(acc[kk]);
            mA = fmaxf(mA, v.x); mB = fmaxf(mB, v.y);
        }
        float sA = 0.f, sB = 0.f;
#pragma unroll
        for (int kk = 0; kk < 25; kk++) {
            float2 v = unpack2(acc[kk]);
            float eA = __expf(v.x - mA), eB = __expf(v.y - mB);
            sA += eA; sB += eB;
            acc[kk] = pack2(eA, eB);
        }
        ull iv = pack2(__fdividef(1.f, sA), __fdividef(1.f, sB));
#pragma unroll
        for (int kk = 0; kk < 25; kk++)
            acc[kk] = mul2(acc[kk], iv);
    }

    // ---- transpose probs to smem: ps[kk][lp] (overwrites crs) ----
    __syncthreads();
#pragma unroll
    for (int kk = 0; kk < 25; kk++)
        *(ull*)&ps[kk * PSS + lp0] = acc[kk];
    __syncthreads();

    // ---- out = attn @ Wg: warp w -> rows 2w,2w+1; lane l -> d=l, d=l+32 ----
    {
        int w = t >> 5, l = t & 31;
        ull wr0[25], wr1[25];
#pragma unroll
        for (int kk = 0; kk < 25; kk++) {
            float w0 = Wgs[kk * 64 + l];
            float w1 = Wgs[kk * 64 + 32 + l];
            wr0[kk] = pack2(w0, w0);
            wr1[kk] = pack2(w1, w1);
        }
#pragma unroll 1
        for (int rr = 0; rr < 2; rr++) {
            int lrow = w * 2 + rr;
            int lpbase = lrow * TW;
            size_t grow = ((size_t)b * 256 + by * TH + lrow) * 256 + bx * TW;
            float* outp = out + grow * 64;
#pragma unroll 1
            for (int ii = 0; ii < 8; ii++) {
                ull oa0 = 0, oa1 = 0, ob0 = 0, ob1 = 0;
                const float* psp = ps + lpbase + ii * 4;
#pragma unroll
                for (int kk = 0; kk < 25; kk++) {
                    ulonglong2 pq = *(const ulonglong2*)(psp + kk * PSS);
                    oa0 = fma2(pq.x, wr0[kk], oa0);
                    oa1 = fma2(pq.x, wr1[kk], oa1);
                    ob0 = fma2(pq.y, wr0[kk], ob0);
                    ob1 = fma2(pq.y, wr1[kk], ob1);
                }
                float2 a0 = unpack2(oa0), a1 = unpack2(oa1);
                float2 b0 = unpack2(ob0), b1 = unpack2(ob1);
                float* o0 = outp + (ii * 4) * 64;
                o0[l]       = a0.x;   // px+0, d=l
                o0[64 + l]  = a0.y;   // px+1, d=l
                o0[32 + l]  = a1.x;   // px+0, d=l+32
                o0[96 + l]  = a1.y;   // px+1, d=l+32
                o0[128 + l] = b0.x;   // px+2, d=l
                o0[192 + l] = b0.y;   // px+3, d=l
                o0[160 + l] = b1.x;   // px+2, d=l+32
                o0[224 + l] = b1.y;   // px+3, d=l+32
            }
        }
    }
}

// ---------------- launch ----------------
extern "C" void kernel_launch(void* const* d_in, const int* in_sizes, int n_in,
                              void* d_out, int out_size)
{
    const float* main_in = (const float*)d_in[0];
    const float* ref_in  = (const float*)d_in[1];
    const float* Wm      = (const float*)d_in[2];
    const float* Wr      = (const float*)d_in[3];
    const float* Wg      = (const float*)d_in[4];
    float* out = (float*)d_out;

    compute_M_kernel<<<16, 256>>>(Wm, Wr);
    conv_kernel<<<2048, 128>>>(ref_in);

    const int smem_bytes = (UNION_FLOATS + 1600) * 4;  // 58,400 B
    cudaFuncSetAttribute(attn10_kernel, cudaFuncAttributeMaxDynamicSharedMemorySize, smem_bytes);
    attn10_kernel<<<dim3(8, 16, 4), 256, smem_bytes>>>(main_in, Wg, out);
}